// round 10
// baseline (speedup 1.0000x reference)
#include <cuda_runtime.h>
#include <stdint.h>

// VDEmbedding: out[t,:] = (x[t]==0 ? 0 : mask[x[t]]) * weight[x[t], :]
// x: int32 [65536], weight: f32 [128000,128], mask: f32 [128000] -> out: f32 [65536,128]
//
// R9: L1 bypass for all bulk traffic. L1tex is the top counter in EVERY profile
// (30-41%) while gather rows have ~0 reuse (L1D is also flushed per launch) and
// stores are write-once. __ldcg/__stcg (.cg = L2-only, no L1 allocate) remove
// ~67MB from the L1 data path; only idx/mask loads still use L1.
// Body = proven-best R1 shape: 1 warp/token, one float4 per lane.

static constexpr int EMBED_DIM = 128;
static constexpr int PAD_IDX   = 0;

__global__ __launch_bounds__(256, 8)
void vdemb_kernel(const int* __restrict__ x,
                  const float* __restrict__ weight,
                  const float* __restrict__ mask,
                  float* __restrict__ out,
                  int n_tokens)
{
    int warp_in_block = threadIdx.x >> 5;
    int lane = threadIdx.x & 31;
    int token = blockIdx.x * (blockDim.x >> 5) + warp_in_block;
    if (token >= n_tokens) return;

    int idx = __ldg(&x[token]);                       // L1 ok: broadcast, tiny
    float s = (idx == PAD_IDX) ? 0.0f : __ldg(&mask[idx]);  // L1 ok: tiny

    // row gather: L2-only (no useless L1 allocate)
    const float4* wrow = reinterpret_cast<const float4*>(weight + (size_t)idx * EMBED_DIM);
    float4 w = __ldcg(&wrow[lane]);

    float4 o;
    o.x = s * w.x;
    o.y = s * w.y;
    o.z = s * w.z;
    o.w = s * w.w;

    // store: L2-only (write-once, keep it out of L1)
    float4* orow = reinterpret_cast<float4*>(out + (size_t)token * EMBED_DIM);
    __stcg(&orow[lane], o);
}

extern "C" void kernel_launch(void* const* d_in, const int* in_sizes, int n_in,
                              void* d_out, int out_size)
{
    const int*   x      = (const int*)d_in[0];
    const float* weight = (const float*)d_in[1];
    const float* mask   = (const float*)d_in[2];
    float*       out    = (float*)d_out;

    int n_tokens = in_sizes[0];           // 65536
    int warps_per_block = 256 / 32;       // 8 tokens per block
    int blocks = (n_tokens + warps_per_block - 1) / warps_per_block;  // 8192

    vdemb_kernel<<<blocks, 256>>>(x, weight, mask, out, n_tokens);
}

// round 11
// speedup vs baseline: 1.1557x; 1.1557x over previous
#include <cuda_runtime.h>
#include <stdint.h>

// VDEmbedding: out[t,:] = (x[t]==0 ? 0 : mask[x[t]]) * weight[x[t], :]
// x: int32 [65536], weight: f32 [128000,128], mask: f32 [128000] -> out: f32 [65536,128]
//
// R10: break the per-warp dependent chain (idx -> mask -> row). Phase 1: 64
// threads resolve all (idx, scale) pairs for the block in parallel into smem.
// Phase 2: warps read (idx,s) via cheap LDS and issue back-to-back row gathers
// (4 independent LDG.128 per thread in flight) -> effective in-flight bytes
// ~10x higher than the chained versions, which were latency-bound at 12KB/SM.

static constexpr int EMBED_DIM = 128;
static constexpr int PAD_IDX   = 0;
static constexpr int TOK_PER_BLOCK = 64;
static constexpr int THREADS   = 256;
static constexpr int TOK_PER_WARP = TOK_PER_BLOCK / (THREADS / 32);  // 8
static constexpr int BATCH = 4;  // unroll depth of phase-2 gathers

__global__ __launch_bounds__(THREADS, 8)
void vdemb_kernel(const int* __restrict__ x,
                  const float* __restrict__ weight,
                  const float* __restrict__ mask,
                  float* __restrict__ out,
                  int n_tokens)
{
    __shared__ int   s_idx[TOK_PER_BLOCK];
    __shared__ float s_scl[TOK_PER_BLOCK];

    int tid  = threadIdx.x;
    int warp = tid >> 5;
    int lane = tid & 31;
    int base = blockIdx.x * TOK_PER_BLOCK;

    // Phase 1: resolve (idx, scale) for all 64 tokens, 64 parallel chains.
    if (tid < TOK_PER_BLOCK) {
        int t = base + tid;
        int idx = (t < n_tokens) ? __ldg(&x[t]) : PAD_IDX;
        float s = (idx == PAD_IDX) ? 0.0f : __ldg(&mask[idx]);
        s_idx[tid] = idx;
        s_scl[tid] = s;
    }
    __syncthreads();

    // Phase 2: pure gather stream. Each warp: 8 tokens, 2 batches of 4.
    int tok0 = warp * TOK_PER_WARP;
#pragma unroll
    for (int b = 0; b < TOK_PER_WARP / BATCH; b++) {
        int idx[BATCH];
        float s[BATCH];
#pragma unroll
        for (int i = 0; i < BATCH; i++) {
            int tl = tok0 + b * BATCH + i;
            idx[i] = s_idx[tl];
            s[i]   = s_scl[tl];
        }

        float4 w[BATCH];
#pragma unroll
        for (int i = 0; i < BATCH; i++) {
            const float4* wrow =
                reinterpret_cast<const float4*>(weight + (size_t)idx[i] * EMBED_DIM);
            w[i] = __ldg(&wrow[lane]);
        }

#pragma unroll
        for (int i = 0; i < BATCH; i++) {
            int t = base + tok0 + b * BATCH + i;
            float4 o;
            o.x = s[i] * w[i].x;
            o.y = s[i] * w[i].y;
            o.z = s[i] * w[i].z;
            o.w = s[i] * w[i].w;
            float4* orow = reinterpret_cast<float4*>(out + (size_t)t * EMBED_DIM);
            orow[lane] = o;
        }
    }
}

extern "C" void kernel_launch(void* const* d_in, const int* in_sizes, int n_in,
                              void* d_out, int out_size)
{
    const int*   x      = (const int*)d_in[0];
    const float* weight = (const float*)d_in[1];
    const float* mask   = (const float*)d_in[2];
    float*       out    = (float*)d_out;

    int n_tokens = in_sizes[0];                              // 65536
    int blocks = (n_tokens + TOK_PER_BLOCK - 1) / TOK_PER_BLOCK;  // 1024

    vdemb_kernel<<<blocks, THREADS>>>(x, weight, mask, out, n_tokens);
}